// round 6
// baseline (speedup 1.0000x reference)
#include <cuda_runtime.h>
#include <cstdint>

// ============================================================================
// Problem constants
// ============================================================================
#define M_TOTAL   32768
#define N_TOTAL   1024
#define K_TOTAL   1024
#define THRESH    0.05f

// ---- M split between engines
#define M_MMA     16384                 // rows via mma.sync (tensor pipe)
#define M_DP      16384                 // rows via dp4a (fma pipe)

// ---- mma engine tiling
#define TILE_M    128
#define TILE_N    128
#define TILE_K    64
#define NUM_KC    (K_TOTAL / TILE_K)    // 16
#define STAGES    3
#define ROW_BYTES 80
#define STAGE_BYTES ((TILE_M + TILE_N) * ROW_BYTES)   // 20480
#define SMEM_TOTAL  (STAGES * STAGE_BYTES)            // 61440
#define MMA_CTAS  ((M_MMA / TILE_M) * (N_TOTAL / TILE_N))   // 1024

// ---- dp4a engine tiling: CTA 64M x 64N, 256 thr (16x16), thread 4x4
#define DTILE_M   64
#define DTILE_N   64
#define DP_PITCH  68                    // 64B data + 4B (2-way LDS conflicts max)
#define DP_HALF   (DTILE_M * DP_PITCH)  // 4352
#define DP_STAGE  (2 * DP_HALF)         // 8704 (A + B), double-buffered = 17408
#define DP_CTAS   ((M_DP / DTILE_M) * (N_TOTAL / DTILE_N))  // 4096

#define TOTAL_CTAS (MMA_CTAS + DP_CTAS)   // 5120 (1 mma : 4 dp4a)

// ============================================================================
// Scratch (device globals — no runtime allocation)
// ============================================================================
__device__ int8_t g_xq[(size_t)M_TOTAL * K_TOTAL];   // 32 MiB (all rows)
__device__ int8_t g_wq[(size_t)N_TOTAL * K_TOTAL];   // 1 MiB

// ============================================================================
// Helpers
// ============================================================================
__device__ __forceinline__ uint32_t smem_u32(const void* p) {
    uint32_t a;
    asm("{ .reg .u64 t; cvta.to.shared.u64 t, %1; cvt.u32.u64 %0, t; }"
        : "=r"(a) : "l"(p));
    return a;
}

#define CP_ASYNC16(dst_u32, gsrc) \
    asm volatile("cp.async.cg.shared.global [%0], [%1], 16;" \
                 :: "r"(dst_u32), "l"(gsrc) : "memory")
#define CP_ASYNC4(dst_u32, gsrc) \
    asm volatile("cp.async.ca.shared.global [%0], [%1], 4;" \
                 :: "r"(dst_u32), "l"(gsrc) : "memory")
#define CP_ASYNC_COMMIT() asm volatile("cp.async.commit_group;" ::: "memory")
#define CP_ASYNC_WAIT(n)  asm volatile("cp.async.wait_group %0;" :: "n"(n) : "memory")

__device__ __forceinline__ void mma_s8(int* c, const uint32_t* a, const uint32_t* b) {
    asm volatile(
        "mma.sync.aligned.m16n8k32.row.col.s32.s8.s8.s32 "
        "{%0,%1,%2,%3}, {%4,%5,%6,%7}, {%8,%9}, {%0,%1,%2,%3};"
        : "+r"(c[0]), "+r"(c[1]), "+r"(c[2]), "+r"(c[3])
        : "r"(a[0]), "r"(a[1]), "r"(a[2]), "r"(a[3]), "r"(b[0]), "r"(b[1]));
}

__device__ __forceinline__ void ldsm_x4(uint32_t* r, uint32_t addr) {
    asm volatile("ldmatrix.sync.aligned.m8n8.x4.shared.b16 {%0,%1,%2,%3}, [%4];"
        : "=r"(r[0]), "=r"(r[1]), "=r"(r[2]), "=r"(r[3]) : "r"(addr));
}

__device__ __forceinline__ int8_t tq(float v) {
    return (fabsf(v) < THRESH) ? (int8_t)0 : (v > 0.f ? (int8_t)1 : (int8_t)-1);
}

// ============================================================================
// Prep: one kernel quantizes BOTH x and w (fp32 -> ternary int8, 16/thread)
// ============================================================================
#define N16_X ((M_TOTAL * K_TOTAL) / 16)   // 2,097,152
#define N16_W ((N_TOTAL * K_TOTAL) / 16)   // 65,536
#define N16_TOTAL (N16_X + N16_W)          // 2,162,688

__global__ __launch_bounds__(256) void prep_kernel(
    const float* __restrict__ x, const float* __restrict__ w)
{
    int i = blockIdx.x * blockDim.x + threadIdx.x;
    if (i >= N16_TOTAL) return;
    const float4* src;
    int4* dst;
    if (i < N16_X) {
        src = (const float4*)x + i * 4;
        dst = (int4*)g_xq + i;
    } else {
        int j = i - N16_X;
        src = (const float4*)w + j * 4;
        dst = (int4*)g_wq + j;
    }
    int8_t r[16];
    #pragma unroll
    for (int j = 0; j < 4; j++) {
        float4 v = src[j];
        r[j * 4 + 0] = tq(v.x);
        r[j * 4 + 1] = tq(v.y);
        r[j * 4 + 2] = tq(v.z);
        r[j * 4 + 3] = tq(v.w);
    }
    *dst = *reinterpret_cast<int4*>(r);
}

// ============================================================================
// Engine 1: mma.sync int8 CTA (rows [0, M_MMA))
// ============================================================================
__device__ __forceinline__ void mma_cta(int idx, char* smem, float* __restrict__ out)
{
    const int tid  = threadIdx.x;
    const int lane = tid & 31;
    const int wid  = tid >> 5;
    const int wm   = wid & 3;
    const int wn   = wid >> 2;

    const int m0 = (idx >> 3) * TILE_M;
    const int n0 = (idx & 7) * TILE_N;

    const uint64_t xg = __cvta_generic_to_global(g_xq);
    const uint64_t wg = __cvta_generic_to_global(g_wq);
    const uint32_t sbase = smem_u32(smem);

    const int g8 = lane >> 3, t8 = lane & 7;
    const uint32_t a_lane = (uint32_t)((t8 + ((g8 & 1) << 3)) * ROW_BYTES + ((g8 >> 1) << 4));
    const uint32_t b_lane = (uint32_t)((t8 + ((g8 >> 1) << 3)) * ROW_BYTES + ((g8 & 1) << 4));

    auto load_stage = [&](int kc, int s) {
        uint32_t sb = sbase + s * STAGE_BYTES;
        #pragma unroll
        for (int t = 0; t < 2; t++) {
            int i = tid + t * 256;
            int row = i >> 2, seg = i & 3;
            uint64_t src = xg + (uint64_t)(m0 + row) * K_TOTAL + kc * TILE_K + seg * 16;
            CP_ASYNC16(sb + row * ROW_BYTES + seg * 16, src);
        }
        #pragma unroll
        for (int t = 0; t < 2; t++) {
            int i = tid + t * 256;
            int row = i >> 2, seg = i & 3;
            uint64_t src = wg + (uint64_t)(n0 + row) * K_TOTAL + kc * TILE_K + seg * 16;
            CP_ASYNC16(sb + (TILE_M + row) * ROW_BYTES + seg * 16, src);
        }
        CP_ASYNC_COMMIT();
    };

    int acc[2][8][4];
    #pragma unroll
    for (int mi = 0; mi < 2; mi++)
        #pragma unroll
        for (int ni = 0; ni < 8; ni++)
            #pragma unroll
            for (int q = 0; q < 4; q++) acc[mi][ni][q] = 0;

    load_stage(0, 0);
    load_stage(1, 1);

    for (int kc = 0; kc < NUM_KC; kc++) {
        if (kc + STAGES - 1 < NUM_KC) CP_ASYNC_WAIT(STAGES - 2);
        else                          CP_ASYNC_WAIT(0);
        __syncthreads();

        const uint32_t stage = sbase + (kc % STAGES) * STAGE_BYTES;
        const uint32_t sa  = stage + (uint32_t)(wm * 32) * ROW_BYTES + a_lane;
        const uint32_t sbB = stage + (uint32_t)(TILE_M + wn * 64) * ROW_BYTES + b_lane;

        #pragma unroll
        for (int kk = 0; kk < 2; kk++) {
            const uint32_t ko = (uint32_t)(kk * 32);
            uint32_t a[2][4];
            ldsm_x4(a[0], sa + ko);
            ldsm_x4(a[1], sa + 16 * ROW_BYTES + ko);
            uint32_t b[4][4];
            #pragma unroll
            for (int p = 0; p < 4; p++)
                ldsm_x4(b[p], sbB + (uint32_t)(p * 16) * ROW_BYTES + ko);
            #pragma unroll
            for (int mi = 0; mi < 2; mi++)
                #pragma unroll
                for (int ni = 0; ni < 8; ni++)
                    mma_s8(acc[mi][ni], a[mi], &b[ni >> 1][(ni & 1) * 2]);
        }

        if (kc + STAGES - 1 < NUM_KC)
            load_stage(kc + STAGES - 1, (kc + STAGES - 1) % STAGES);
    }

    #pragma unroll
    for (int mi = 0; mi < 2; mi++) {
        const int r = m0 + wm * 32 + mi * 16 + (lane >> 2);
        #pragma unroll
        for (int ni = 0; ni < 8; ni++) {
            const int c = n0 + wn * 64 + ni * 8 + (lane & 3) * 2;
            float2 v0 = make_float2((float)acc[mi][ni][0], (float)acc[mi][ni][1]);
            float2 v1 = make_float2((float)acc[mi][ni][2], (float)acc[mi][ni][3]);
            *(float2*)(out + (size_t)r * N_TOTAL + c)       = v0;
            *(float2*)(out + (size_t)(r + 8) * N_TOTAL + c) = v1;
        }
    }
}

// ============================================================================
// Engine 2: dp4a CTA (rows [M_MMA, M_TOTAL)) — fma pipe
// 64x64 tile, 256 threads (16x16), thread 4x4, K chunked 64B, double-buffered.
// ============================================================================
__device__ __forceinline__ void dp_cta(int idx, char* smem, float* __restrict__ out)
{
    const int tid = threadIdx.x;
    const int tx = tid & 15;
    const int ty = tid >> 4;

    const int mt = idx >> 4;           // 0..255 (n fastest -> L2 reuse of x rows)
    const int nt = idx & 15;
    const int m0 = mt * DTILE_M;       // offset within dp rows
    const int n0 = nt * DTILE_N;

    const uint64_t xg = __cvta_generic_to_global(g_xq) + (uint64_t)M_MMA * K_TOTAL;
    const uint64_t wg = __cvta_generic_to_global(g_wq);
    const uint32_t sbase = smem_u32(smem);

    // stage fill: A 64x64B + B 64x64B as 4B cp.async (pitch 68 in SMEM)
    auto load_stage = [&](int kc, int s) {
        uint32_t sb = sbase + s * DP_STAGE;
        #pragma unroll
        for (int t = 0; t < 4; t++) {          // A: 1024 words
            int i = tid + t * 256;
            int row = i >> 4, w = i & 15;
            uint64_t src = xg + (uint64_t)(m0 + row) * K_TOTAL + kc * 64 + w * 4;
            CP_ASYNC4(sb + row * DP_PITCH + w * 4, src);
        }
        #pragma unroll
        for (int t = 0; t < 4; t++) {          // B: 1024 words
            int i = tid + t * 256;
            int row = i >> 4, w = i & 15;
            uint64_t src = wg + (uint64_t)(n0 + row) * K_TOTAL + kc * 64 + w * 4;
            CP_ASYNC4(sb + DP_HALF + row * DP_PITCH + w * 4, src);
        }
        CP_ASYNC_COMMIT();
    };

    int acc[4][4];
    #pragma unroll
    for (int i = 0; i < 4; i++)
        #pragma unroll
        for (int j = 0; j < 4; j++) acc[i][j] = 0;

    load_stage(0, 0);

    for (int kc = 0; kc < NUM_KC; kc++) {
        const int s = kc & 1;
        if (kc + 1 < NUM_KC) { load_stage(kc + 1, s ^ 1); CP_ASYNC_WAIT(1); }
        else                 { CP_ASYNC_WAIT(0); }
        __syncthreads();

        const char* aS = smem + s * DP_STAGE + (ty * 4) * DP_PITCH;
        const char* bS = smem + s * DP_STAGE + DP_HALF + (tx * 4) * DP_PITCH;

        #pragma unroll
        for (int w = 0; w < 16; w++) {
            int a[4], b[4];
            #pragma unroll
            for (int i = 0; i < 4; i++)
                a[i] = *(const int*)(aS + i * DP_PITCH + w * 4);
            #pragma unroll
            for (int j = 0; j < 4; j++)
                b[j] = *(const int*)(bS + j * DP_PITCH + w * 4);
            #pragma unroll
            for (int i = 0; i < 4; i++)
                #pragma unroll
                for (int j = 0; j < 4; j++)
                    acc[i][j] = __dp4a(a[i], b[j], acc[i][j]);
        }
        __syncthreads();   // all reads of stage s done before it is refilled
    }

    #pragma unroll
    for (int i = 0; i < 4; i++) {
        const int r = M_MMA + m0 + ty * 4 + i;
        float4 v;
        v.x = (float)acc[i][0];
        v.y = (float)acc[i][1];
        v.z = (float)acc[i][2];
        v.w = (float)acc[i][3];
        *(float4*)(out + (size_t)r * N_TOTAL + n0 + tx * 4) = v;
    }
}

// ============================================================================
// Fused GEMM: interleave 1 mma CTA per 4 dp4a CTAs
// ============================================================================
__global__ __launch_bounds__(256, 2) void ternary_gemm_kernel(float* __restrict__ out)
{
    extern __shared__ char smem[];
    const int bid = (int)blockIdx.x;
    const int q = bid / 5;
    const int r = bid - q * 5;
    if (r == 0) mma_cta(q, smem, out);                 // q in [0, 1024)
    else        dp_cta(4 * q + (r - 1), smem, out);    // in [0, 4096)
}

// ============================================================================
// Launch (2 launches per call -> ncu -s5 lands on the GEMM)
// ============================================================================
extern "C" void kernel_launch(void* const* d_in, const int* in_sizes, int n_in,
                              void* d_out, int out_size)
{
    const float* x = (const float*)d_in[0];
    const float* w = (const float*)d_in[1];
    float* out = (float*)d_out;

    prep_kernel<<<(N16_TOTAL + 255) / 256, 256>>>(x, w);

    static bool attr_set = false;
    if (!attr_set) {
        cudaFuncSetAttribute(ternary_gemm_kernel,
                             cudaFuncAttributeMaxDynamicSharedMemorySize, SMEM_TOTAL);
        attr_set = true;
    }
    ternary_gemm_kernel<<<TOTAL_CTAS, 256, SMEM_TOTAL>>>(out);
}